// round 2
// baseline (speedup 1.0000x reference)
#include <cuda_runtime.h>
#include <cstdint>

#define Hc 128
#define Nc 128
#define Lc 2048

// Scratch for synthesized kernel Kl[h,l]  (1 MB) — referenced directly by kernels.
__device__ float g_Kl[Hc * Lc];

// ---------------------------------------------------------------------------
// Kernel 1: Kl[h,l] = sum_n C[h,n] * K[l,h,n]
// warp-per-(h,l): lane loads float4 of K row (512B contiguous per warp),
// C[h] float4 per lane (L2-resident), shfl reduction.
// ---------------------------------------------------------------------------
__global__ __launch_bounds__(256) void kl_synth_kernel(
    const float* __restrict__ K,   // (L,H,N)
    const float* __restrict__ C)   // (H,N)
{
    const int h    = blockIdx.y;
    const int warp = threadIdx.x >> 5;
    const int lane = threadIdx.x & 31;
    const int l    = blockIdx.x * 8 + warp;

    const float4 c4 = reinterpret_cast<const float4*>(C + h * Nc)[lane];
    const size_t base = ((size_t)l * Hc + h) * Nc;
    const float4 k4 = reinterpret_cast<const float4*>(K + base)[lane];

    float s = c4.x * k4.x + c4.y * k4.y + c4.z * k4.z + c4.w * k4.w;
    #pragma unroll
    for (int o = 16; o > 0; o >>= 1)
        s += __shfl_xor_sync(0xFFFFFFFFu, s, o);

    if (lane == 0) g_Kl[h * Lc + l] = s;
}

// ---------------------------------------------------------------------------
// Kernel 2: depthwise 'same' convolution + skip.
//   y[h,t] = sum_{m=0}^{L-1} Kl[h,m] * u[h, t + 1023 - m] + D[h]*u[h,t]
// One block per channel. Kl and zero-padded u live in shared memory.
// u is stored SKEWED: loc(a) = a + (a>>3) so that lane-stride-8 reads
// (outputs are 8-consecutive per thread) hit 32 distinct banks.
// Each thread: 8 consecutive outputs, sliding register window of 8 u-values
// -> per m-step: 8 FFMA + 1 broadcast LDS + 1 conflict-free LDS.
// ---------------------------------------------------------------------------
#define PAD_OFF 1032                 // u-index -1032 maps to a=0
#define SU_SIZE 4616                 // skew(4102) = 4614 -> 4616 floats

__device__ __forceinline__ int skew(int a) { return a + (a >> 3); }

__global__ __launch_bounds__(256) void conv_kernel(
    const float* __restrict__ u,   // (H,L)
    const float* __restrict__ D,   // (H,)
    float* __restrict__ y)         // (H,L)
{
    __shared__ float sk[Lc];
    __shared__ float su[SU_SIZE];

    const int h   = blockIdx.x;
    const int tid = threadIdx.x;          // 256 threads

    // Load Kl[h,:] into shared (coalesced float4)
    {
        const float4* src = reinterpret_cast<const float4*>(g_Kl + h * Lc);
        float4* dst = reinterpret_cast<float4*>(sk);
        for (int i = tid; i < Lc / 4; i += 256) dst[i] = src[i];
    }
    // Zero the padded/skewed u array
    for (int i = tid; i < SU_SIZE; i += 256) su[i] = 0.0f;
    __syncthreads();
    // Fill valid u values at skewed locations
    for (int i = tid; i < Lc; i += 256) {
        int a = i + PAD_OFF;
        su[skew(a)] = u[h * Lc + i];
    }
    __syncthreads();

    const int t0 = tid * 8;              // 8 consecutive outputs per thread

    // Sliding window registers: w[j] = u[t0 + 1023 - m + j] (current m)
    float w[8];
    #pragma unroll
    for (int j = 0; j < 8; ++j) {
        int a = t0 + 1023 + j + PAD_OFF;
        w[j] = su[skew(a)];
    }

    float acc[8];
    #pragma unroll
    for (int j = 0; j < 8; ++j) acc[j] = 0.0f;

    #pragma unroll 8
    for (int m = 0; m < Lc; ++m) {
        const float kv = sk[m];
        #pragma unroll
        for (int j = 0; j < 8; ++j)
            acc[j] = fmaf(kv, w[j], acc[j]);
        // shift window: v_j(m+1) = v_{j-1}(m); fresh v_0 = u[t0 + 1022 - m]
        #pragma unroll
        for (int j = 7; j > 0; --j) w[j] = w[j - 1];
        int a = t0 + 1022 - m + PAD_OFF;
        w[0] = su[skew(a)];
    }

    // Skip connection + store (two float4 stores, aligned since t0 % 8 == 0)
    const float dh = D[h];
    const float4* ug = reinterpret_cast<const float4*>(u + h * Lc + t0);
    float4 u0 = ug[0], u1 = ug[1];
    float4 o0, o1;
    o0.x = acc[0] + dh * u0.x;  o0.y = acc[1] + dh * u0.y;
    o0.z = acc[2] + dh * u0.z;  o0.w = acc[3] + dh * u0.w;
    o1.x = acc[4] + dh * u1.x;  o1.y = acc[5] + dh * u1.y;
    o1.z = acc[6] + dh * u1.z;  o1.w = acc[7] + dh * u1.w;
    float4* og = reinterpret_cast<float4*>(y + h * Lc + t0);
    og[0] = o0;
    og[1] = o1;
}

// ---------------------------------------------------------------------------
extern "C" void kernel_launch(void* const* d_in, const int* in_sizes, int n_in,
                              void* d_out, int out_size)
{
    // Identify inputs by element count (sizes are pairwise distinct):
    //   u: H*L = 262144, C: H*N = 16384, D: H = 128, K: L*H*N = 33554432
    const float* u = nullptr;
    const float* C = nullptr;
    const float* D = nullptr;
    const float* K = nullptr;
    for (int i = 0; i < n_in; ++i) {
        switch (in_sizes[i]) {
            case Hc * Lc:              u = (const float*)d_in[i]; break;
            case Hc * Nc:              C = (const float*)d_in[i]; break;
            case Hc:                   D = (const float*)d_in[i]; break;
            default:
                if (in_sizes[i] == Lc * Hc * Nc) K = (const float*)d_in[i];
                break;
        }
    }

    float* y = (float*)d_out;

    dim3 grid1(Lc / 8, Hc);
    kl_synth_kernel<<<grid1, 256>>>(K, C);
    conv_kernel<<<Hc, 256>>>(u, D, y);
}